// round 4
// baseline (speedup 1.0000x reference)
#include <cuda_runtime.h>
#include <cstdint>

// PointIntegrator: volume-rendering composite.
// N=2, R=65536 -> 131072 rays, K=64 samples, C=16 channels.
// One warp per ray. Lane l owns sample pair (2l, 2l+1).
//
// Outputs (flat, concatenated in reference order):
//   [0, 2097152)          composite_color   [ray][16]
//   [2097152, 2228224)    composite_radial  [ray]
//   [2228224, 10485760)   weights           [ray][63]
//   [10485760, 10616832)  T_end             [ray]

#define NRAYS   131072
#define KDIM    64
#define CDIM    16
#define T_EPS_F 1e-10f

#define OFF_COLOR 0u
#define OFF_RAD   2097152u
#define OFF_W     2228224u
#define OFF_TEND  10485760u

__device__ unsigned int g_rm_max_bits;

// Global max of radii midpoints. radii sorted ascending per ray, so the
// per-ray max midpoint is 0.5*(r[62]+r[63]).
__global__ void rmmax_kernel(const float* __restrict__ radii) {
    int ray = blockIdx.x * blockDim.x + threadIdx.x;
    float m = 0.0f;
    if (ray < NRAYS) {
        float a = radii[(size_t)ray * KDIM + 62];
        float b = radii[(size_t)ray * KDIM + 63];
        m = 0.5f * (a + b);
    }
#pragma unroll
    for (int d = 16; d > 0; d >>= 1)
        m = fmaxf(m, __shfl_xor_sync(0xffffffffu, m, d));
    if ((threadIdx.x & 31) == 0)
        atomicMax(&g_rm_max_bits, __float_as_uint(m));  // positive floats: uint order ok
}

__global__ void __launch_bounds__(256)
integrate_kernel(const float* __restrict__ colors,
                 const float* __restrict__ dens,
                 const float* __restrict__ radii,
                 float* __restrict__ out) {
    const unsigned FULL = 0xffffffffu;
    int ray  = (int)((blockIdx.x * blockDim.x + threadIdx.x) >> 5);
    int lane = threadIdx.x & 31;

    // ---------- Phase 1: per-pair alphas ----------
    const float2 rr = ((const float2*)(radii + (size_t)ray * KDIM))[lane];
    const float2 dd = ((const float2*)(dens  + (size_t)ray * KDIM))[lane];
    float r2 = __shfl_down_sync(FULL, rr.x, 1);   // radii[2l+2] (lane31: self, unused)
    float d2 = __shfl_down_sync(FULL, dd.x, 1);   // dens [2l+2]

    float dm0 = fmaxf(0.5f * (dd.x + dd.y), 0.0f);
    float e0  = expf(-(rr.y - rr.x) * dm0);
    float a0  = 1.0f - e0;
    float f0  = e0 + T_EPS_F;

    float dm1 = fmaxf(0.5f * (dd.y + d2), 0.0f);
    float e1  = expf(-(r2 - rr.y) * dm1);
    float a1  = 1.0f - e1;
    float f1  = e1 + T_EPS_F;
    if (lane == 31) { a1 = 0.0f; f1 = 1.0f; }     // k=63 does not exist

    // ---------- Phase 2: exclusive prefix product (transmittance) ----------
    float p    = f0 * f1;
    float incl = p;
#pragma unroll
    for (int d = 1; d < 32; d <<= 1) {
        float t = __shfl_up_sync(FULL, incl, d);
        if (lane >= d) incl *= t;
    }
    float excl = __shfl_up_sync(FULL, incl, 1);
    if (lane == 0) excl = 1.0f;

    float t_end = __shfl_sync(FULL, excl, 31);    // T[62] = prod f_0..f_61

    float w0 = a0 * excl;                         // w[2l]   = a * T[2l]
    float w1 = a1 * (excl * f0);                  // w[2l+1] = a * T[2l+1] (lane31: 0)

    // ---------- radial + weight-sum partials ----------
    float rm0 = 0.5f * (rr.x + rr.y);
    float rm1 = 0.5f * (rr.y + r2);
    float pw = w0 + w1;
    float pr = fmaf(w0, rm0, w1 * rm1);
#pragma unroll
    for (int d = 16; d > 0; d >>= 1) {
        pw += __shfl_xor_sync(FULL, pw, d);
        pr += __shfl_xor_sync(FULL, pr, d);
    }

    // ---------- u coefficients: 2*sum_k w_k*c_m[k] = sum_j (w_{j-1}+w_j)*c_j ----------
    auto getw = [&](int j) -> float {
        float va = __shfl_sync(FULL, w0, (j >> 1) & 31);
        float vb = __shfl_sync(FULL, w1, (j >> 1) & 31);
        float v  = (j & 1) ? vb : va;
        return (j >= 0 && j <= 62) ? v : 0.0f;
    };
    float wl   = getw(lane);         // w[lane]       (for coalesced weight store)
    float wh   = getw(lane + 32);    // w[lane+32]
    float u_lo = getw(lane - 1) + wl;     // u[lane]
    float u_hi = getw(lane + 31) + wh;    // u[lane+32]

    // ---------- Phase 3: color accumulation (rows lane, lane+32) ----------
    const float* cbase = colors + (size_t)ray * (KDIM * CDIM) + (size_t)lane * CDIM;
    float4 l0 = ((const float4*)cbase)[0];
    float4 l1 = ((const float4*)cbase)[1];
    float4 l2 = ((const float4*)cbase)[2];
    float4 l3 = ((const float4*)cbase)[3];
    const float* cbh = cbase + 32 * CDIM;
    float4 h0 = ((const float4*)cbh)[0];
    float4 h1 = ((const float4*)cbh)[1];
    float4 h2 = ((const float4*)cbh)[2];
    float4 h3 = ((const float4*)cbh)[3];

    float acc[16];
    acc[0]  = fmaf(u_hi, h0.x, u_lo * l0.x);
    acc[1]  = fmaf(u_hi, h0.y, u_lo * l0.y);
    acc[2]  = fmaf(u_hi, h0.z, u_lo * l0.z);
    acc[3]  = fmaf(u_hi, h0.w, u_lo * l0.w);
    acc[4]  = fmaf(u_hi, h1.x, u_lo * l1.x);
    acc[5]  = fmaf(u_hi, h1.y, u_lo * l1.y);
    acc[6]  = fmaf(u_hi, h1.z, u_lo * l1.z);
    acc[7]  = fmaf(u_hi, h1.w, u_lo * l1.w);
    acc[8]  = fmaf(u_hi, h2.x, u_lo * l2.x);
    acc[9]  = fmaf(u_hi, h2.y, u_lo * l2.y);
    acc[10] = fmaf(u_hi, h2.z, u_lo * l2.z);
    acc[11] = fmaf(u_hi, h2.w, u_lo * l2.w);
    acc[12] = fmaf(u_hi, h3.x, u_lo * l3.x);
    acc[13] = fmaf(u_hi, h3.y, u_lo * l3.y);
    acc[14] = fmaf(u_hi, h3.z, u_lo * l3.z);
    acc[15] = fmaf(u_hi, h3.w, u_lo * l3.w);

#pragma unroll
    for (int d = 16; d > 0; d >>= 1) {
#pragma unroll
        for (int c = 0; c < 16; ++c)
            acc[c] += __shfl_xor_sync(FULL, acc[c], d);
    }

    // ---------- Stores ----------
    float* wbase = out + OFF_W + (size_t)ray * 63;
    wbase[lane] = wl;                              // w[0..31]
    if (lane < 31) wbase[lane + 32] = wh;          // w[32..62]

    if (lane == 0) {
        float rmmax = __uint_as_float(g_rm_max_bits);
        float ratio = (pw > 0.0f) ? fminf(pr / pw, rmmax) : rmmax;
        out[OFF_RAD  + ray] = ratio;
        out[OFF_TEND + ray] = t_end;

        float4* oc = (float4*)(out + OFF_COLOR + (size_t)ray * CDIM);
        oc[0] = make_float4(acc[0]  - 1.0f, acc[1]  - 1.0f, acc[2]  - 1.0f, acc[3]  - 1.0f);
        oc[1] = make_float4(acc[4]  - 1.0f, acc[5]  - 1.0f, acc[6]  - 1.0f, acc[7]  - 1.0f);
        oc[2] = make_float4(acc[8]  - 1.0f, acc[9]  - 1.0f, acc[10] - 1.0f, acc[11] - 1.0f);
        oc[3] = make_float4(acc[12] - 1.0f, acc[13] - 1.0f, acc[14] - 1.0f, acc[15] - 1.0f);
    }
}

extern "C" void kernel_launch(void* const* d_in, const int* in_sizes, int n_in,
                              void* d_out, int out_size) {
    const float* colors = (const float*)d_in[0];
    const float* dens   = (const float*)d_in[1];
    const float* radii  = (const float*)d_in[2];
    float* out = (float*)d_out;

    void* sym = nullptr;
    cudaGetSymbolAddress(&sym, g_rm_max_bits);
    cudaMemsetAsync(sym, 0, sizeof(unsigned int));

    rmmax_kernel<<<(NRAYS + 255) / 256, 256>>>(radii);

    // 8 warps (rays) per 256-thread block -> 16384 blocks
    integrate_kernel<<<NRAYS / 8, 256>>>(colors, dens, radii, out);
}

// round 5
// speedup vs baseline: 1.2146x; 1.2146x over previous
#include <cuda_runtime.h>
#include <cstdint>

// PointIntegrator: volume-rendering composite.
// N=2, R=65536 -> 131072 rays, K=64 samples, C=16 channels.
// One warp per ray. Lane j owns sample pair (2j, 2j+1) for the scan;
// color pass is channel-major: lane = h*16+c accumulates channel c over
// rows [h*32, h*32+32) with perfectly coalesced scalar loads.
//
// Outputs (flat, concatenated in reference order):
//   [0, 2097152)          composite_color   [ray][16]
//   [2097152, 2228224)    composite_radial  [ray]
//   [2228224, 10485760)   weights           [ray][63]
//   [10485760, 10616832)  T_end             [ray]

#define NRAYS   131072
#define KDIM    64
#define CDIM    16
#define T_EPS_F 1e-10f

#define OFF_COLOR 0u
#define OFF_RAD   2097152u
#define OFF_W     2228224u
#define OFF_TEND  10485760u

__device__ unsigned int g_rm_max_bits;

// Global max of radii midpoints. radii sorted ascending per ray, so the
// per-ray max midpoint is 0.5*(r[62]+r[63]).
__global__ void rmmax_kernel(const float* __restrict__ radii) {
    int ray = blockIdx.x * blockDim.x + threadIdx.x;
    float m = 0.0f;
    if (ray < NRAYS) {
        float a = radii[(size_t)ray * KDIM + 62];
        float b = radii[(size_t)ray * KDIM + 63];
        m = 0.5f * (a + b);
    }
#pragma unroll
    for (int d = 16; d > 0; d >>= 1)
        m = fmaxf(m, __shfl_xor_sync(0xffffffffu, m, d));
    if ((threadIdx.x & 31) == 0)
        atomicMax(&g_rm_max_bits, __float_as_uint(m));  // positive floats: uint order ok
}

__global__ void __launch_bounds__(256)
integrate_kernel(const float* __restrict__ colors,
                 const float* __restrict__ dens,
                 const float* __restrict__ radii,
                 float* __restrict__ out) {
    const unsigned FULL = 0xffffffffu;
    int ray  = (int)((blockIdx.x * blockDim.x + threadIdx.x) >> 5);
    int lane = threadIdx.x & 31;

    // ---------- Phase 1: per-pair alphas (lane j owns samples 2j, 2j+1) ----------
    const float2 rr = ((const float2*)(radii + (size_t)ray * KDIM))[lane];
    const float2 dd = ((const float2*)(dens  + (size_t)ray * KDIM))[lane];
    float r2 = __shfl_down_sync(FULL, rr.x, 1);   // radii[2j+2] (lane31: self, unused)
    float d2 = __shfl_down_sync(FULL, dd.x, 1);   // dens [2j+2]

    float dm0 = fmaxf(0.5f * (dd.x + dd.y), 0.0f);
    float e0  = expf(-(rr.y - rr.x) * dm0);
    float a0  = 1.0f - e0;
    float f0  = e0 + T_EPS_F;

    float dm1 = fmaxf(0.5f * (dd.y + d2), 0.0f);
    float e1  = expf(-(r2 - rr.y) * dm1);
    float a1  = 1.0f - e1;
    float f1  = e1 + T_EPS_F;
    if (lane == 31) { a1 = 0.0f; f1 = 1.0f; }     // interval k=63 does not exist

    // ---------- Phase 2: exclusive prefix product (transmittance) ----------
    float incl = f0 * f1;
#pragma unroll
    for (int d = 1; d < 32; d <<= 1) {
        float t = __shfl_up_sync(FULL, incl, d);
        if (lane >= d) incl *= t;
    }
    float excl = __shfl_up_sync(FULL, incl, 1);
    if (lane == 0) excl = 1.0f;
    // T_end = T[62] = prod f_0..f_61 = excl at lane 31 (stored directly below).

    float w0 = a0 * excl;                         // w[2j]   = a * T[2j]
    float w1 = a1 * (excl * f0);                  // w[2j+1] = a * T[2j+1] (lane31: 0)

    // ---------- radial + weight-sum reductions (packed 2-in-1 tree) ----------
    float rm0 = 0.5f * (rr.x + rr.y);
    float rm1 = 0.5f * (rr.y + r2);
    float pw = w0 + w1;                            // partial weight sum
    float pr = fmaf(w0, rm0, w1 * rm1);            // partial radial sum
    {
        bool hi = (lane & 16) != 0;
        float send = hi ? pw : pr;
        float r = __shfl_xor_sync(FULL, send, 16);
        float s = (hi ? pr : pw) + r;              // lanes 0-15: pw, 16-31: pr
#pragma unroll
        for (int d = 8; d > 0; d >>= 1)
            s += __shfl_xor_sync(FULL, s, d);
        pw = s;                                    // valid in lanes 0-15
        pr = __shfl_sync(FULL, s, 16 + (lane & 15)); // pr-sum delivered to low lanes
    }

    // ---------- u coefficients (local!): u[2j]=w[2j-1]+w[2j], u[2j+1]=w[2j]+w[2j+1] ----------
    float wprev = __shfl_up_sync(FULL, w1, 1);     // w[2j-1]
    if (lane == 0) wprev = 0.0f;                   // w[-1] = 0
    float u_even = wprev + w0;                     // u[2j]
    float u_odd  = w0 + w1;                        // u[2j+1]  (lane31: u[63]=w[62])

    // ---------- Phase 3: channel-major color accumulation ----------
    // lane = h*16 + c :  accumulate channel c over rows h*32 .. h*32+31.
    // Warp per iteration reads two contiguous 64B chunks -> ~1 L1 wavefront.
    int h = lane >> 4;                             // 0 or 1
    int c = lane & 15;
    const float* cp = colors + (size_t)ray * (KDIM * CDIM) + (size_t)(h * 32) * CDIM + c;
    int usrc = (h << 4);                           // h*16, + (i>>1) per iter

    float acc0 = 0.0f, acc1 = 0.0f;
#pragma unroll
    for (int i = 0; i < 32; i += 2) {
        float ue = __shfl_sync(FULL, u_even, usrc + (i >> 1));   // u[h*32 + i]
        float uo = __shfl_sync(FULL, u_odd,  usrc + (i >> 1));   // u[h*32 + i + 1]
        acc0 = fmaf(ue, cp[(size_t)i * CDIM],       acc0);
        acc1 = fmaf(uo, cp[(size_t)(i + 1) * CDIM], acc1);
    }
    float acc = acc0 + acc1;
    acc += __shfl_xor_sync(FULL, acc, 16);         // combine row-halves; all lanes hold channel (lane&15)

    // ---------- Stores ----------
    // weights: zipped layout, predicated scalar stores (63 per ray)
    float* wbase = out + OFF_W + (size_t)ray * 63;
    wbase[2 * lane] = w0;
    if (lane < 31) wbase[2 * lane + 1] = w1;

    // composite color: 16 lanes, 64B coalesced
    if (lane < 16)
        out[OFF_COLOR + (size_t)ray * CDIM + c] = acc - 1.0f;

    if (lane == 0) {
        float rmmax = __uint_as_float(g_rm_max_bits);
        float ratio = (pw > 0.0f) ? fminf(pr / pw, rmmax) : rmmax;
        out[OFF_RAD + ray] = ratio;
    }
    if (lane == 31)
        out[OFF_TEND + ray] = excl;                // T_end

}

extern "C" void kernel_launch(void* const* d_in, const int* in_sizes, int n_in,
                              void* d_out, int out_size) {
    const float* colors = (const float*)d_in[0];
    const float* dens   = (const float*)d_in[1];
    const float* radii  = (const float*)d_in[2];
    float* out = (float*)d_out;

    void* sym = nullptr;
    cudaGetSymbolAddress(&sym, g_rm_max_bits);
    cudaMemsetAsync(sym, 0, sizeof(unsigned int));

    rmmax_kernel<<<(NRAYS + 255) / 256, 256>>>(radii);

    // 8 warps (rays) per 256-thread block -> 16384 blocks
    integrate_kernel<<<NRAYS / 8, 256>>>(colors, dens, radii, out);
}

// round 6
// speedup vs baseline: 1.2183x; 1.0031x over previous
#include <cuda_runtime.h>
#include <cstdint>

// PointIntegrator: volume-rendering composite.
// N=2, R=65536 -> 131072 rays, K=64 samples, C=16 channels.
// One warp per ray. Lane j owns sample pair (2j, 2j+1) for the scan;
// color pass: lane = g*8+c2 accumulates channels (2c2,2c2+1) over rows
// [g*16, g*16+16) with coalesced float2 loads.
//
// Clip analysis: for pw>0, pr/pw is a convex combination of this ray's
// radii midpoints => always inside [global min, global max]; clip never
// binds. Global max only matters for degenerate rays (pw==0 -> nan -> inf
// -> clip to global max). Those are recorded and patched by a tiny fixup
// kernel; the expensive prologue pass over radii is gone.
//
// Outputs (flat, concatenated in reference order):
//   [0, 2097152)          composite_color   [ray][16]
//   [2097152, 2228224)    composite_radial  [ray]
//   [2228224, 10485760)   weights           [ray][63]
//   [10485760, 10616832)  T_end             [ray]

#define NRAYS   131072
#define KDIM    64
#define CDIM    16
#define T_EPS_F 1e-10f

#define OFF_COLOR 0u
#define OFF_RAD   2097152u
#define OFF_W     2228224u
#define OFF_TEND  10485760u

#define DEGEN_CAP 4096

struct DegenState {
    unsigned int rm_max_bits;   // global max of radii midpoints (uint-ordered)
    unsigned int count;         // number of degenerate rays
    unsigned int list[DEGEN_CAP];
};
__device__ DegenState g_degen;

__global__ void __launch_bounds__(256)
integrate_kernel(const float* __restrict__ colors,
                 const float* __restrict__ dens,
                 const float* __restrict__ radii,
                 float* __restrict__ out) {
    const unsigned FULL = 0xffffffffu;
    int ray  = (int)((blockIdx.x * blockDim.x + threadIdx.x) >> 5);
    int lane = threadIdx.x & 31;
    int warp = threadIdx.x >> 5;

    __shared__ float s_rm[8];

    // ---------- Phase 1: per-pair alphas (lane j owns samples 2j, 2j+1) ----------
    const float2 rr = ((const float2*)(radii + (size_t)ray * KDIM))[lane];
    const float2 dd = ((const float2*)(dens  + (size_t)ray * KDIM))[lane];
    float r2 = __shfl_down_sync(FULL, rr.x, 1);   // radii[2j+2] (lane31: self, unused)
    float d2 = __shfl_down_sync(FULL, dd.x, 1);   // dens [2j+2]

    float dm0 = fmaxf(0.5f * (dd.x + dd.y), 0.0f);
    float e0  = expf(-(rr.y - rr.x) * dm0);
    float a0  = 1.0f - e0;
    float f0  = e0 + T_EPS_F;

    float dm1 = fmaxf(0.5f * (dd.y + d2), 0.0f);
    float e1  = expf(-(r2 - rr.y) * dm1);
    float a1  = 1.0f - e1;
    float f1  = e1 + T_EPS_F;
    if (lane == 31) { a1 = 0.0f; f1 = 1.0f; }     // interval k=63 does not exist

    // per-ray max midpoint = 0.5*(r62+r63) = rm0 at lane 31 (radii sorted)
    float rm0 = 0.5f * (rr.x + rr.y);
    float rm1 = 0.5f * (rr.y + r2);
    if (lane == 31) s_rm[warp] = rm0;

    // ---------- Phase 2: exclusive prefix product (transmittance) ----------
    float incl = f0 * f1;
#pragma unroll
    for (int d = 1; d < 32; d <<= 1) {
        float t = __shfl_up_sync(FULL, incl, d);
        if (lane >= d) incl *= t;
    }
    float excl = __shfl_up_sync(FULL, incl, 1);
    if (lane == 0) excl = 1.0f;
    // T_end = T[62] = prod f_0..f_61 = excl at lane 31.

    float w0 = a0 * excl;                         // w[2j]   = a * T[2j]
    float w1 = a1 * (excl * f0);                  // w[2j+1] = a * T[2j+1] (lane31: 0)

    // ---------- radial + weight-sum reductions (packed 2-in-1 tree) ----------
    float pw = w0 + w1;                            // partial weight sum
    float pr = fmaf(w0, rm0, w1 * rm1);            // partial radial sum
    {
        bool hi = (lane & 16) != 0;
        float send = hi ? pw : pr;
        float r = __shfl_xor_sync(FULL, send, 16);
        float s = (hi ? pr : pw) + r;              // lanes 0-15: pw, 16-31: pr
#pragma unroll
        for (int d = 8; d > 0; d >>= 1)
            s += __shfl_xor_sync(FULL, s, d);
        pw = s;                                    // valid in lanes 0-15
        pr = __shfl_sync(FULL, s, 16 + (lane & 15)); // pr-sum delivered to low lanes
    }

    // ---------- u coefficients (local): u[2j]=w[2j-1]+w[2j], u[2j+1]=w[2j]+w[2j+1] ----------
    float wprev = __shfl_up_sync(FULL, w1, 1);     // w[2j-1]
    if (lane == 0) wprev = 0.0f;                   // w[-1] = 0
    float u_even = wprev + w0;                     // u[2j]
    float u_odd  = w0 + w1;                        // u[2j+1]  (lane31: u[63]=w[62])

    // ---------- Phase 3: color accumulation, float2 channel pairs ----------
    // lane = g*8 + c2 : channels (2c2, 2c2+1), rows g*16 .. g*16+15.
    // Warp per iteration covers 4 rows x 64B contiguous float2s.
    int g  = lane >> 3;                            // row group 0..3
    int c2 = lane & 7;                             // channel pair
    const float* cp = colors + (size_t)ray * (KDIM * CDIM)
                             + (size_t)(g * 16) * CDIM + 2 * c2;
    int usrc = lane & 24;                          // g*8; + (i>>1) per iter

    float2 acc = make_float2(0.0f, 0.0f);
#pragma unroll
    for (int i = 0; i < 16; ++i) {
        // row r = g*16+i ; j = r>>1 = g*8 + (i>>1) ; parity = i&1
        float u = __shfl_sync(FULL, (i & 1) ? u_odd : u_even, usrc + (i >> 1));
        float2 cv = *(const float2*)(cp + (size_t)i * CDIM);
        acc.x = fmaf(u, cv.x, acc.x);
        acc.y = fmaf(u, cv.y, acc.y);
    }
    // reduce over the 4 row groups (xor 8, 16)
#pragma unroll
    for (int d = 8; d <= 16; d <<= 1) {
        acc.x += __shfl_xor_sync(FULL, acc.x, d);
        acc.y += __shfl_xor_sync(FULL, acc.y, d);
    }

    // ---------- Stores ----------
    // weights: zipped layout, contiguous 252B per ray
    float* wbase = out + OFF_W + (size_t)ray * 63;
    wbase[2 * lane] = w0;
    if (lane < 31) wbase[2 * lane + 1] = w1;

    // composite color: 8 lanes x float2 = 64B coalesced
    if (lane < 8)
        *(float2*)(out + OFF_COLOR + (size_t)ray * CDIM + 2 * c2) =
            make_float2(acc.x - 1.0f, acc.y - 1.0f);

    if (lane == 0) {
        if (pw > 0.0f) {
            out[OFF_RAD + ray] = pr / pw;
        } else {
            out[OFF_RAD + ray] = 0.0f;             // patched by fixup kernel
            unsigned int idx = atomicAdd(&g_degen.count, 1u);
            if (idx < DEGEN_CAP) g_degen.list[idx] = (unsigned int)ray;
        }
    }
    if (lane == 31)
        out[OFF_TEND + ray] = excl;                // T_end

    // block max of per-ray midpoints -> one atomic per block
    __syncthreads();
    if (threadIdx.x == 0) {
        float m = s_rm[0];
#pragma unroll
        for (int i = 1; i < 8; ++i) m = fmaxf(m, s_rm[i]);
        atomicMax(&g_degen.rm_max_bits, __float_as_uint(m)); // positive floats: uint order ok
    }
}

// Patch degenerate rays (almost always zero of them) with the global max midpoint.
__global__ void fixup_kernel(float* __restrict__ out) {
    unsigned int n = g_degen.count;
    if (n > DEGEN_CAP) n = DEGEN_CAP;
    float v = __uint_as_float(g_degen.rm_max_bits);
    for (unsigned int i = threadIdx.x; i < n; i += blockDim.x)
        out[OFF_RAD + g_degen.list[i]] = v;
}

extern "C" void kernel_launch(void* const* d_in, const int* in_sizes, int n_in,
                              void* d_out, int out_size) {
    const float* colors = (const float*)d_in[0];
    const float* dens   = (const float*)d_in[1];
    const float* radii  = (const float*)d_in[2];
    float* out = (float*)d_out;

    void* sym = nullptr;
    cudaGetSymbolAddress(&sym, g_degen);
    cudaMemsetAsync(sym, 0, 2 * sizeof(unsigned int));   // rm_max_bits + count

    // 8 warps (rays) per 256-thread block -> 16384 blocks
    integrate_kernel<<<NRAYS / 8, 256>>>(colors, dens, radii, out);

    fixup_kernel<<<1, 128>>>(out);
}